// round 13
// baseline (speedup 1.0000x reference)
#include <cuda_runtime.h>
#include <math.h>

#define BB 8
#define DD 512
#define NHH 8
#define HDD 64
#define HH 2048
#define NLL 2
#define VV 32000
#define SMAX 64
#define EPSL 1e-5f
#define NB 128
#define NT 256

typedef unsigned long long ull;

__device__ float g_pe[SMAX*DD];
__device__ float g_x[BB*DD];
__device__ float g_x2[BB*DD];
__device__ float g_q[BB*DD];
__device__ float g_att[BB*DD];
__device__ float g_proj[BB*DD];
__device__ float g_hbuf[BB*HH];
__device__ float g_f2[BB*DD];
__device__ float g_kc[NLL*BB*NHH*SMAX*HDD];   // write-once rows -> normal ld/st
__device__ float g_vc[NLL*BB*NHH*SMAX*HDD];
__device__ float g_cavec[NLL*BB*DD];          // write-once -> normal
__device__ ull   g_amax[2*BB];                // parity-indexed argmax keys
__device__ unsigned g_blk[NB*64];             // per-block arrival counters (monotonic)
__device__ unsigned g_cnt;                    // global arrive counter (monotonic)
__device__ unsigned g_flags[32*64];           // release flags, 256B apart (monotonic)

__device__ __forceinline__ float wred(float v) {
    v += __shfl_xor_sync(0xffffffffu, v, 16);
    v += __shfl_xor_sync(0xffffffffu, v, 8);
    v += __shfl_xor_sync(0xffffffffu, v, 4);
    v += __shfl_xor_sync(0xffffffffu, v, 2);
    v += __shfl_xor_sync(0xffffffffu, v, 1);
    return v;
}

__device__ __forceinline__ void red_release(unsigned* p) {
    asm volatile("red.release.gpu.global.add.u32 [%0], 1;" :: "l"(p) : "memory");
}
__device__ __forceinline__ unsigned ld_acq(const unsigned* p) {
    unsigned v;
    asm volatile("ld.acquire.gpu.global.u32 %0, [%1];" : "=r"(v) : "l"(p) : "memory");
    return v;
}
__device__ __forceinline__ void st_rel(unsigned* p, unsigned v) {
    asm volatile("st.release.gpu.global.u32 [%0], %1;" :: "l"(p), "r"(v) : "memory");
}

// Fence-free grid barrier (NO CCTL.IVALL => L1 stays warm).
// Per-thread red.release to the block counter releases each thread's own
// prior stores; acquire chain: tid0 ld.acquire(blk) -> atom.acq_rel(cnt) ->
// st.release(flags) -> ld.acquire(flag). Mutable shared data is accessed
// via .cg (L2) so no L1 invalidation is ever needed. Monotonic counters
// keep it launch-idempotent for graph replay.
__device__ __forceinline__ void gsync(unsigned &gen, int bx) {
    unsigned target = gen + 1;
    red_release(&g_blk[bx * 64]);                     // all threads
    if (threadIdx.x == 0) {
        while ((int)(ld_acq(&g_blk[bx * 64]) - NT * target) < 0) { }
        unsigned old;
        asm volatile("atom.add.acq_rel.gpu.global.u32 %0, [%1], %2;"
                     : "=r"(old) : "l"(&g_cnt), "r"(1u) : "memory");
        if (old == NB * target - 1u) {
            #pragma unroll
            for (int i = 0; i < 32; i++) st_rel(&g_flags[i * 64], target);
        } else {
            while ((int)(ld_acq(&g_flags[(bx & 31) * 64]) - target) < 0) { }
        }
    }
    gen = target;
    __syncthreads();
}

__device__ __forceinline__ ull ffma2(ull a, ull b, ull c) {
    ull d;
    asm("fma.rn.f32x2 %0, %1, %2, %3;" : "=l"(d) : "l"(a), "l"(b), "l"(c));
    return d;
}
__device__ __forceinline__ float f2sum(ull a) {
    return __uint_as_float((unsigned)a) + __uint_as_float((unsigned)(a >> 32));
}
__device__ __forceinline__ ull pack2(unsigned lo, unsigned hi) {
    ull r;
    asm("mov.b64 %0, {%1, %2};" : "=l"(r) : "r"(lo), "r"(hi));
    return r;
}

__device__ __forceinline__ void lnorm(float4* y, const float* gam, const float* bet, int lane) {
    float s = 0.f;
    #pragma unroll
    for (int k = 0; k < 4; k++) s += y[k].x + y[k].y + y[k].z + y[k].w;
    float m = wred(s) * (1.f / DD);
    float v = 0.f;
    #pragma unroll
    for (int k = 0; k < 4; k++) {
        float a = y[k].x - m, b = y[k].y - m, c = y[k].z - m, d = y[k].w - m;
        v += a * a + b * b + c * c + d * d;
    }
    v = wred(v) * (1.f / DD);
    float r = 1.f / sqrtf(v + EPSL);
    #pragma unroll
    for (int k = 0; k < 4; k++) {
        float4 g = ((const float4*)gam)[lane + 32 * k];
        float4 b4 = ((const float4*)bet)[lane + 32 * k];
        y[k].x = (y[k].x - m) * r * g.x + b4.x;
        y[k].y = (y[k].y - m) * r * g.y + b4.y;
        y[k].z = (y[k].z - m) * r * g.z + b4.z;
        y[k].w = (y[k].w - m) * r * g.w + b4.w;
    }
}

// weight rows via normal loads (L1-resident across phases/steps)
__device__ __forceinline__ void dot8(const float* __restrict__ w, const float* xs,
                                     int lane, float* acc) {
    const float4* w4 = (const float4*)w;
    const float4* x4 = (const float4*)xs;
    #pragma unroll
    for (int k = 0; k < 4; k++) {
        float4 ww = w4[lane + 32 * k];
        #pragma unroll
        for (int b = 0; b < 8; b++) {
            float4 h = x4[b * 128 + lane + 32 * k];
            acc[b] += ww.x * h.x + ww.y * h.y + ww.z * h.z + ww.w * h.w;
        }
    }
}

// butterfly-merge: lane L ends with the full sum of a[L&7]
__device__ __forceinline__ float red8m(float* a, int lane) {
    #pragma unroll
    for (int s = 0; s < 3; s++) {
        int off = 1 << s, n = 8 >> (s + 1);
        #pragma unroll
        for (int i = 0; i < n; i++) {
            float x = (lane & off) ? a[2 * i] : a[2 * i + 1];
            float rc = __shfl_xor_sync(0xffffffffu, x, off);
            a[i] = ((lane & off) ? a[2 * i + 1] : a[2 * i]) + rc;
        }
    }
    float v = a[0];
    v += __shfl_xor_sync(0xffffffffu, v, 8);
    v += __shfl_xor_sync(0xffffffffu, v, 16);
    return v;
}
__device__ __forceinline__ float red4m(float* a, int lane) {
    #pragma unroll
    for (int s = 0; s < 2; s++) {
        int off = 1 << s, n = 4 >> (s + 1);
        #pragma unroll
        for (int i = 0; i < n; i++) {
            float x = (lane & off) ? a[2 * i] : a[2 * i + 1];
            float rc = __shfl_xor_sync(0xffffffffu, x, off);
            a[i] = ((lane & off) ? a[2 * i + 1] : a[2 * i]) + rc;
        }
    }
    float v = a[0];
    v += __shfl_xor_sync(0xffffffffu, v, 4);
    v += __shfl_xor_sync(0xffffffffu, v, 8);
    v += __shfl_xor_sync(0xffffffffu, v, 16);
    return v;
}

__device__ __forceinline__ int amax_tok(ull key) {
    return (int)(0xFFFFFFFFu - (unsigned)(key & 0xFFFFFFFFull));
}

__global__ void __launch_bounds__(NT)
kmain(const float* __restrict__ memory, const float* __restrict__ emb,
      const float* __restrict__ sa_in_w, const float* __restrict__ sa_in_b,
      const float* __restrict__ sa_out_w, const float* __restrict__ sa_out_b,
      const float* __restrict__ ca_in_w, const float* __restrict__ ca_in_b,
      const float* __restrict__ ca_out_w, const float* __restrict__ ca_out_b,
      const float* __restrict__ ff1_w, const float* __restrict__ ff1_b,
      const float* __restrict__ ff2_w, const float* __restrict__ ff2_b,
      const float* __restrict__ ln1_g, const float* __restrict__ ln1_b,
      const float* __restrict__ ln2_g, const float* __restrict__ ln2_b,
      const float* __restrict__ ln3_g, const float* __restrict__ ln3_b,
      const float* __restrict__ out_w, const float* __restrict__ out_b,
      float* __restrict__ tok_out, float* __restrict__ log_out, int L, int wt)
{
    __shared__ __align__(16) float xs[BB * HH / 2];   // 32KB staging
    __shared__ ull sbest[BB];
    int tid = threadIdx.x, lane = tid & 31, warp = tid >> 5;
    int bx = blockIdx.x, gw = bx * 8 + warp, gtid = bx * NT + tid;

    // launch-idempotent: read quiescent generation
    unsigned gen = ld_acq(&g_flags[(bx & 31) * 64]);

    // ---- setup: PE table (write-once -> normal), argmax slots ----
    for (int i = gtid; i < SMAX * DD; i += NB * NT) {
        int d = i & 511;
        double dv = exp((double)(d & ~1) * (-9.210340371976184 / 512.0));
        float arg = (float)(i >> 9) * (float)dv;
        g_pe[i] = (d & 1) ? cosf(arg) : sinf(arg);
    }
    if (gtid < 2 * BB) __stcg(&g_amax[gtid], 0ull);
    gsync(gen, bx);

    // ---- cross-attn constant (Sk=1 => softmax==1), write-once -> normal ----
    if (bx < NLL * BB) {
        int l = bx >> 3, b = bx & 7;
        const float4* m4 = (const float4*)(memory + b * DD);
        for (int j = warp; j < DD; j += 8) {
            const float4* w4 = (const float4*)(ca_in_w + ((size_t)l * 3 * DD + 2 * DD + j) * DD);
            float acc = 0.f;
            #pragma unroll
            for (int k = 0; k < 4; k++) {
                float4 w = w4[lane + 32 * k], x = m4[lane + 32 * k];
                acc += w.x * x.x + w.y * x.y + w.z * x.z + w.w * x.w;
            }
            acc = wred(acc);
            if (lane == 0) xs[j] = acc + ca_in_b[l * 3 * DD + 2 * DD + j];
        }
        __syncthreads();
        for (int j = warp; j < DD; j += 8) {
            const float4* w4 = (const float4*)(ca_out_w + ((size_t)l * DD + j) * DD);
            const float4* v4 = (const float4*)xs;
            float acc = 0.f;
            #pragma unroll
            for (int k = 0; k < 4; k++) {
                float4 w = w4[lane + 32 * k], x = v4[lane + 32 * k];
                acc += w.x * x.x + w.y * x.y + w.z * x.z + w.w * x.w;
            }
            acc = wred(acc);
            if (lane == 0) g_cavec[(l * BB + b) * DD + j] = acc + ca_out_b[l * DD + j];
        }
    }
    gsync(gen, bx);

    for (int t = 0; t < L; t++) {
        int par = t & 1;
        for (int l = 0; l < NLL; l++) {
            // ---- QKV: 96 blocks, 768 warps x exactly 2 rows ----
            if (bx < 96) {
                int b = warp;
                float4 y[4];
                if (l == 0) {
                    int tok = (t == 0) ? 1 : amax_tok(__ldcg(&g_amax[(1 - par) * BB + b]));
                    if (bx == 0 && tid < BB) {
                        if (t > 0 && wt)
                            tok_out[tid * L + (t - 1)] =
                                (float)amax_tok(__ldcg(&g_amax[(1 - par) * BB + tid]));
                        __stcg(&g_amax[par * BB + tid], 0ull);
                    }
                    const float4* e4 = (const float4*)(emb + (size_t)tok * DD);
                    const float4* p4 = (const float4*)(g_pe + t * DD);
                    #pragma unroll
                    for (int k = 0; k < 4; k++) {
                        float4 e = e4[lane + 32 * k], p = p4[lane + 32 * k];
                        y[k] = make_float4(e.x + p.x, e.y + p.y, e.z + p.z, e.w + p.w);
                    }
                } else {
                    #pragma unroll
                    for (int k = 0; k < 4; k++) {
                        float4 a = __ldcg(((const float4*)(g_x2 + b * DD)) + lane + 32 * k);
                        float4 c = __ldcg(((const float4*)(g_f2 + b * DD)) + lane + 32 * k);
                        y[k] = make_float4(a.x + c.x, a.y + c.y, a.z + c.z, a.w + c.w);
                    }
                    lnorm(y, ln3_g + (l - 1) * DD, ln3_b + (l - 1) * DD, lane);
                }
                #pragma unroll
                for (int k = 0; k < 4; k++) {
                    ((float4*)xs)[b * 128 + lane + 32 * k] = y[k];
                    if (bx == 0) __stcg(((float4*)g_x) + b * 128 + lane + 32 * k, y[k]);
                }
                __syncthreads();
                #pragma unroll
                for (int rr = 0; rr < 2; rr++) {
                    int j = gw + rr * 768;
                    float acc[8] = {0, 0, 0, 0, 0, 0, 0, 0};
                    dot8(sa_in_w + ((size_t)l * 3 * DD + j) * DD, xs, lane, acc);
                    float val = red8m(acc, lane);
                    if (lane < 8) {
                        val += sa_in_b[l * 3 * DD + j];
                        if (j < DD) __stcg(&g_q[lane * DD + j], val);
                        else if (j < 2 * DD) {
                            int h = (j - DD) >> 6, d = (j - DD) & 63;
                            g_kc[(((l * BB + lane) * NHH + h) * SMAX + t) * HDD + d] = val;
                        } else {
                            int h = (j - 2 * DD) >> 6, d = (j - 2 * DD) & 63;
                            g_vc[(((l * BB + lane) * NHH + h) * SMAX + t) * HDD + d] = val;
                        }
                    }
                }
            }
            gsync(gen, bx);

            // ---- self-attn: 64 blocks, one (b,h) each; K/V rows L1-resident ----
            if (bx < 64) {
                int b = bx >> 3, h = bx & 7, n = t + 1;
                float* psh = xs;            // 64 probs (zero-padded)
                float* osh = xs + 64;       // 8 x 64 partial PV outputs
                const float* kb = g_kc + (size_t)(((l * BB + b) * NHH + h) * SMAX) * HDD;
                const float* vb = g_vc + (size_t)(((l * BB + b) * NHH + h) * SMAX) * HDD;
                if (warp == 0) {
                    float4 qv[16];
                    #pragma unroll
                    for (int k = 0; k < 16; k++)
                        qv[k] = __ldcg(((const float4*)(g_q + b * DD + h * HDD)) + k);
                    float s0 = -1e30f, s1 = -1e30f;
                    if (lane < n) {
                        const float4* k4 = (const float4*)(kb + (size_t)lane * HDD);
                        float a = 0.f;
                        #pragma unroll
                        for (int k = 0; k < 16; k++) {
                            float4 kk = k4[k];
                            a += kk.x * qv[k].x + kk.y * qv[k].y + kk.z * qv[k].z + kk.w * qv[k].w;
                        }
                        s0 = a * 0.125f;
                    }
                    if (lane + 32 < n) {
                        const float4* k4 = (const float4*)(kb + (size_t)(lane + 32) * HDD);
                        float a = 0.f;
                        #pragma unroll
                        for (int k = 0; k < 16; k++) {
                            float4 kk = k4[k];
                            a += kk.x * qv[k].x + kk.y * qv[k].y + kk.z * qv[k].z + kk.w * qv[k].w;
                        }
                        s1 = a * 0.125f;
                    }
                    float m = fmaxf(s0, s1);
                    #pragma unroll
                    for (int off = 16; off; off >>= 1)
                        m = fmaxf(m, __shfl_xor_sync(0xffffffffu, m, off));
                    float p0 = (lane < n) ? expf(s0 - m) : 0.f;
                    float p1 = (lane + 32 < n) ? expf(s1 - m) : 0.f;
                    float sum = wred(p0 + p1);
                    psh[lane] = p0;
                    psh[lane + 32] = p1;
                    if (lane == 0) xs[576] = sum;
                }
                __syncthreads();
                {   // 8 warps split PV (probs zero beyond n)
                    float o0 = 0.f, o1 = 0.f;
                    #pragma unroll
                    for (int i = 0; i < 8; i++) {
                        int j = warp + i * 8;
                        float p = psh[j];
                        o0 += p * vb[(size_t)j * HDD + lane];
                        o1 += p * vb[(size_t)j * HDD + lane + 32];
                    }
                    osh[warp * 64 + lane] = o0;
                    osh[warp * 64 + lane + 32] = o1;
                }
                __syncthreads();
                if (warp == 0) {
                    float inv = 1.f / xs[576];
                    float a0 = 0.f, a1 = 0.f;
                    #pragma unroll
                    for (int w = 0; w < 8; w++) {
                        a0 += osh[w * 64 + lane];
                        a1 += osh[w * 64 + lane + 32];
                    }
                    __stcg(&g_att[b * DD + h * HDD + lane], a0 * inv);
                    __stcg(&g_att[b * DD + h * HDD + lane + 32], a1 * inv);
                }
            }
            gsync(gen, bx);

            // ---- attn out proj: 64 blocks, 512 warps x exactly 1 row ----
            if (bx < 64) {
                for (int i = tid; i < BB * DD / 4; i += NT)
                    ((float4*)xs)[i] = __ldcg(((const float4*)g_att) + i);
                __syncthreads();
                int j = gw;
                float acc[8] = {0, 0, 0, 0, 0, 0, 0, 0};
                dot8(sa_out_w + ((size_t)l * DD + j) * DD, xs, lane, acc);
                float val = red8m(acc, lane);
                if (lane < 8) __stcg(&g_proj[lane * DD + j], val + sa_out_b[l * DD + j]);
            }
            gsync(gen, bx);

            // ---- LN1 -> +cavec -> LN2 -> FFN1: 128 blocks, 1024 warps x 2 rows ----
            {
                int b = warp;
                float4 y[4];
                #pragma unroll
                for (int k = 0; k < 4; k++) {
                    float4 a = __ldcg(((const float4*)(g_x + b * DD)) + lane + 32 * k);
                    float4 c = __ldcg(((const float4*)(g_proj + b * DD)) + lane + 32 * k);
                    y[k] = make_float4(a.x + c.x, a.y + c.y, a.z + c.z, a.w + c.w);
                }
                lnorm(y, ln1_g + l * DD, ln1_b + l * DD, lane);
                #pragma unroll
                for (int k = 0; k < 4; k++) {
                    float4 c = ((const float4*)(g_cavec + (l * BB + b) * DD))[lane + 32 * k];
                    y[k].x += c.x; y[k].y += c.y; y[k].z += c.z; y[k].w += c.w;
                }
                lnorm(y, ln2_g + l * DD, ln2_b + l * DD, lane);
                #pragma unroll
                for (int k = 0; k < 4; k++) {
                    ((float4*)xs)[b * 128 + lane + 32 * k] = y[k];
                    if (bx == 0) __stcg(((float4*)g_x2) + b * 128 + lane + 32 * k, y[k]);
                }
                __syncthreads();
                #pragma unroll
                for (int rr = 0; rr < 2; rr++) {
                    int j = gw + rr * 1024;
                    float acc[8] = {0, 0, 0, 0, 0, 0, 0, 0};
                    dot8(ff1_w + ((size_t)l * HH + j) * DD, xs, lane, acc);
                    float val = red8m(acc, lane);
                    if (lane < 8)
                        __stcg(&g_hbuf[lane * HH + j], fmaxf(val + ff1_b[l * HH + j], 0.f));
                }
            }
            gsync(gen, bx);

            // ---- FFN2: 64 blocks, 512 warps x 1 row per half ----
            if (bx < 64) {
                #pragma unroll
                for (int half = 0; half < 2; half++) {
                    __syncthreads();
                    for (int i = tid; i < 4 * HH / 4; i += NT)
                        ((float4*)xs)[i] = __ldcg(((const float4*)(g_hbuf + half * 4 * HH)) + i);
                    __syncthreads();
                    int j = gw;
                    const float4* w4 = (const float4*)(ff2_w + ((size_t)l * DD + j) * HH);
                    const float4* x4 = (const float4*)xs;
                    float acc[4] = {0, 0, 0, 0};
                    #pragma unroll 4
                    for (int k = 0; k < 16; k++) {
                        float4 w = w4[lane + 32 * k];
                        #pragma unroll
                        for (int b = 0; b < 4; b++) {
                            float4 h = x4[b * 512 + lane + 32 * k];
                            acc[b] += w.x * h.x + w.y * h.y + w.z * h.z + w.w * h.w;
                        }
                    }
                    float val = red4m(acc, lane);
                    if (lane < 4)
                        __stcg(&g_f2[(half * 4 + lane) * DD + j], val + ff2_b[l * DD + j]);
                }
            }
            gsync(gen, bx);
        } // layers

        // ---- logits: 125 blocks, 1000 warps x exactly 8 groups of 4 rows ----
        if (bx < 125) {
            int b = warp;
            float4 y[4];
            #pragma unroll
            for (int k = 0; k < 4; k++) {
                float4 a = __ldcg(((const float4*)(g_x2 + b * DD)) + lane + 32 * k);
                float4 c = __ldcg(((const float4*)(g_f2 + b * DD)) + lane + 32 * k);
                y[k] = make_float4(a.x + c.x, a.y + c.y, a.z + c.z, a.w + c.w);
            }
            lnorm(y, ln3_g + (NLL - 1) * DD, ln3_b + (NLL - 1) * DD, lane);
            #pragma unroll
            for (int k = 0; k < 4; k++)
                ((float4*)xs)[b * 128 + lane + 32 * k] = y[k];
            if (tid < BB) sbest[tid] = 0ull;
            __syncthreads();

            const ulonglong2* hsu = (const ulonglong2*)xs;
            int myb = lane & 7, myr = lane >> 3;
            ull bestk = 0ull;
            #pragma unroll 1
            for (int g = 0; g < 8; g++) {
                int v0 = (gw * 8 + g) * 4;
                const uint4* wu = (const uint4*)(out_w + (size_t)v0 * DD);
                ull acc[4][8];
                #pragma unroll
                for (int r = 0; r < 4; r++)
                    #pragma unroll
                    for (int bb = 0; bb < 8; bb++) acc[r][bb] = 0ull;
                #pragma unroll
                for (int k = 0; k < 4; k++) {
                    ulonglong2 h[8];
                    #pragma unroll
                    for (int bb = 0; bb < 8; bb++) h[bb] = hsu[bb * 128 + lane + 32 * k];
                    #pragma unroll
                    for (int r = 0; r < 4; r++) {
                        uint4 W = __ldcg(wu + r * 128 + lane + 32 * k);  // L1-bypass stream
                        ull wlo = pack2(W.x, W.y), whi = pack2(W.z, W.w);
                        #pragma unroll
                        for (int bb = 0; bb < 8; bb++) {
                            acc[r][bb] = ffma2(wlo, h[bb].x, acc[r][bb]);
                            acc[r][bb] = ffma2(whi, h[bb].y, acc[r][bb]);
                        }
                    }
                }
                float a[32];
                #pragma unroll
                for (int r = 0; r < 4; r++)
                    #pragma unroll
                    for (int bb = 0; bb < 8; bb++) a[r * 8 + bb] = f2sum(acc[r][bb]);
                #pragma unroll
                for (int s = 0; s < 5; s++) {
                    int off = 1 << s, n = 32 >> (s + 1);
                    #pragma unroll
                    for (int i = 0; i < n; i++) {
                        float x = (lane & off) ? a[2 * i] : a[2 * i + 1];
                        float rc = __shfl_xor_sync(0xffffffffu, x, off);
                        a[i] = ((lane & off) ? a[2 * i + 1] : a[2 * i]) + rc;
                    }
                }
                int v = v0 + myr;
                float val = a[0] + out_b[v];
                log_out[((size_t)myb * L + t) * VV + v] = val;
                unsigned u = __float_as_uint(val);
                u = (u & 0x80000000u) ? ~u : (u | 0x80000000u);
                ull key = ((ull)u << 32) | (unsigned)(0xFFFFFFFFu - (unsigned)v);
                if (key > bestk) bestk = key;
            }
            ull o = __shfl_xor_sync(0xffffffffu, bestk, 8);  if (o > bestk) bestk = o;
            o     = __shfl_xor_sync(0xffffffffu, bestk, 16); if (o > bestk) bestk = o;
            if (myr == 0) atomicMax(&sbest[myb], bestk);
            __syncthreads();
            if (tid < BB) atomicMax(&g_amax[par * BB + tid], sbest[tid]);
        }
        gsync(gen, bx);   // doubles as next step's pre-QKV barrier
    } // t

    // final token (decided by step L-1's logits)
    if (bx == 0 && tid < BB && wt)
        tok_out[tid * L + (L - 1)] = (float)amax_tok(__ldcg(&g_amax[((L - 1) & 1) * BB + tid]));
}

extern "C" void kernel_launch(void* const* d_in, const int* in_sizes, int n_in,
                              void* d_out, int out_size) {
    (void)in_sizes; (void)n_in;
    int L, wt;
    if (out_size % (BB * (VV + 1)) == 0) { L = out_size / (BB * (VV + 1)); wt = 1; }
    else if (out_size % (BB * VV) == 0)  { L = out_size / (BB * VV);       wt = 0; }
    else                                 { L = 48;                         wt = 1; }
    if (L > SMAX - 1) L = SMAX - 1;
    if (L <= 0) return;

    float* out_f = (float*)d_out;
    float* tok_out = out_f;
    float* log_out = wt ? (out_f + (size_t)BB * L) : out_f;

    kmain<<<NB, NT>>>(
        (const float*)d_in[0],  (const float*)d_in[1],  (const float*)d_in[2],
        (const float*)d_in[3],  (const float*)d_in[4],  (const float*)d_in[5],
        (const float*)d_in[6],  (const float*)d_in[7],  (const float*)d_in[8],
        (const float*)d_in[9],  (const float*)d_in[10], (const float*)d_in[11],
        (const float*)d_in[12], (const float*)d_in[13], (const float*)d_in[14],
        (const float*)d_in[15], (const float*)d_in[16], (const float*)d_in[17],
        (const float*)d_in[18], (const float*)d_in[19], (const float*)d_in[20],
        (const float*)d_in[21], tok_out, log_out, L, wt);
}

// round 14
// speedup vs baseline: 3.0422x; 3.0422x over previous
#include <cuda_runtime.h>
#include <math.h>

#define BB 8
#define DD 512
#define NHH 8
#define HDD 64
#define HH 2048
#define NLL 2
#define VV 32000
#define SMAX 64
#define EPSL 1e-5f
#define NB 128
#define NT 256

typedef unsigned long long ull;

__device__ float g_pe[SMAX*DD];
__device__ float g_x[BB*DD];
__device__ float g_x2[BB*DD];
__device__ float g_q[BB*DD];
__device__ float g_att[BB*DD];
__device__ float g_proj[BB*DD];
__device__ float g_hbuf[BB*HH];
__device__ float g_f2[BB*DD];
__device__ float g_kc[NLL*BB*NHH*SMAX*HDD];
__device__ float g_vc[NLL*BB*NHH*SMAX*HDD];
__device__ float g_cavec[NLL*BB*DD];
__device__ ull   g_amax[2*16*BB];       // parity x 16 shadow slots x batch
__device__ unsigned g_cnt;              // monotonic arrival counter (never reset)
__device__ unsigned g_flags[32*64];     // release flags, 256B apart (monotonic)

__device__ __forceinline__ float wred(float v) {
    v += __shfl_xor_sync(0xffffffffu, v, 16);
    v += __shfl_xor_sync(0xffffffffu, v, 8);
    v += __shfl_xor_sync(0xffffffffu, v, 4);
    v += __shfl_xor_sync(0xffffffffu, v, 2);
    v += __shfl_xor_sync(0xffffffffu, v, 1);
    return v;
}

// Grid barrier (R11-proven): single release/acquire fence per block (tid0).
// Monotonic counter + distributed flag lines; launch-idempotent via reading
// the quiescent generation at kernel entry (graph replay safe).
__device__ __forceinline__ void gsync(unsigned &gen, int bx) {
    __syncthreads();
    if (threadIdx.x == 0) {
        unsigned target = gen + 1;
        asm volatile("fence.acq_rel.gpu;" ::: "memory");          // release
        if (atomicAdd(&g_cnt, 1u) == NB * target - 1u) {
            asm volatile("fence.acq_rel.gpu;" ::: "memory");
            #pragma unroll
            for (int i = 0; i < 32; i++)
                asm volatile("st.relaxed.gpu.global.u32 [%0], %1;"
                             :: "l"(&g_flags[i * 64]), "r"(target) : "memory");
        } else {
            unsigned cur;
            unsigned* fl = &g_flags[(bx & 31) * 64];
            do {
                asm volatile("ld.relaxed.gpu.global.u32 %0, [%1];"
                             : "=r"(cur) : "l"(fl));
            } while ((int)(cur - target) < 0);                    // wrap-safe
        }
        asm volatile("fence.acq_rel.gpu;" ::: "memory");          // acquire
    }
    gen = gen + 1;
    __syncthreads();
}

__device__ __forceinline__ ull ffma2(ull a, ull b, ull c) {
    ull d;
    asm("fma.rn.f32x2 %0, %1, %2, %3;" : "=l"(d) : "l"(a), "l"(b), "l"(c));
    return d;
}
__device__ __forceinline__ float f2sum(ull a) {
    return __uint_as_float((unsigned)a) + __uint_as_float((unsigned)(a >> 32));
}

__device__ __forceinline__ void lnorm(float4* y, const float* gam, const float* bet, int lane) {
    float s = 0.f;
    #pragma unroll
    for (int k = 0; k < 4; k++) s += y[k].x + y[k].y + y[k].z + y[k].w;
    float m = wred(s) * (1.f / DD);
    float v = 0.f;
    #pragma unroll
    for (int k = 0; k < 4; k++) {
        float a = y[k].x - m, b = y[k].y - m, c = y[k].z - m, d = y[k].w - m;
        v += a * a + b * b + c * c + d * d;
    }
    v = wred(v) * (1.f / DD);
    float r = 1.f / sqrtf(v + EPSL);
    #pragma unroll
    for (int k = 0; k < 4; k++) {
        float4 g = ((const float4*)gam)[lane + 32 * k];
        float4 b4 = ((const float4*)bet)[lane + 32 * k];
        y[k].x = (y[k].x - m) * r * g.x + b4.x;
        y[k].y = (y[k].y - m) * r * g.y + b4.y;
        y[k].z = (y[k].z - m) * r * g.z + b4.z;
        y[k].w = (y[k].w - m) * r * g.w + b4.w;
    }
}

__device__ __forceinline__ void dot8(const float* __restrict__ w, const float* xs,
                                     int lane, float* acc) {
    const float4* w4 = (const float4*)w;
    const float4* x4 = (const float4*)xs;
    #pragma unroll
    for (int k = 0; k < 4; k++) {
        float4 ww = w4[lane + 32 * k];
        #pragma unroll
        for (int b = 0; b < 8; b++) {
            float4 h = x4[b * 128 + lane + 32 * k];
            acc[b] += ww.x * h.x + ww.y * h.y + ww.z * h.z + ww.w * h.w;
        }
    }
}

// butterfly-merge: lane L ends with the full sum of a[L&7]
__device__ __forceinline__ float red8m(float* a, int lane) {
    #pragma unroll
    for (int s = 0; s < 3; s++) {
        int off = 1 << s, n = 8 >> (s + 1);
        #pragma unroll
        for (int i = 0; i < n; i++) {
            float x = (lane & off) ? a[2 * i] : a[2 * i + 1];
            float rc = __shfl_xor_sync(0xffffffffu, x, off);
            a[i] = ((lane & off) ? a[2 * i + 1] : a[2 * i]) + rc;
        }
    }
    float v = a[0];
    v += __shfl_xor_sync(0xffffffffu, v, 8);
    v += __shfl_xor_sync(0xffffffffu, v, 16);
    return v;
}
__device__ __forceinline__ float red4m(float* a, int lane) {
    #pragma unroll
    for (int s = 0; s < 2; s++) {
        int off = 1 << s, n = 4 >> (s + 1);
        #pragma unroll
        for (int i = 0; i < n; i++) {
            float x = (lane & off) ? a[2 * i] : a[2 * i + 1];
            float rc = __shfl_xor_sync(0xffffffffu, x, off);
            a[i] = ((lane & off) ? a[2 * i + 1] : a[2 * i]) + rc;
        }
    }
    float v = a[0];
    v += __shfl_xor_sync(0xffffffffu, v, 4);
    v += __shfl_xor_sync(0xffffffffu, v, 8);
    v += __shfl_xor_sync(0xffffffffu, v, 16);
    return v;
}

__device__ __forceinline__ int amax_tok(ull key) {
    return (int)(0xFFFFFFFFu - (unsigned)(key & 0xFFFFFFFFull));
}

// max over 16 shadow slots for (parity parX, batch b); result on ALL lanes
__device__ __forceinline__ ull amax_slot_max(int parX, int b, int lane) {
    ull k = (lane < 16) ? g_amax[parX * 128 + lane * 8 + b] : 0ull;
    #pragma unroll
    for (int off = 1; off <= 8; off <<= 1) {
        ull o = __shfl_xor_sync(0xffffffffu, k, off);
        if (o > k) k = o;
    }
    ull o = __shfl_xor_sync(0xffffffffu, k, 16);   // propagate to lanes 16..31
    if (o > k) k = o;
    return k;
}

__global__ void __launch_bounds__(NT)
kmain(const float* __restrict__ memory, const float* __restrict__ emb,
      const float* __restrict__ sa_in_w, const float* __restrict__ sa_in_b,
      const float* __restrict__ sa_out_w, const float* __restrict__ sa_out_b,
      const float* __restrict__ ca_in_w, const float* __restrict__ ca_in_b,
      const float* __restrict__ ca_out_w, const float* __restrict__ ca_out_b,
      const float* __restrict__ ff1_w, const float* __restrict__ ff1_b,
      const float* __restrict__ ff2_w, const float* __restrict__ ff2_b,
      const float* __restrict__ ln1_g, const float* __restrict__ ln1_b,
      const float* __restrict__ ln2_g, const float* __restrict__ ln2_b,
      const float* __restrict__ ln3_g, const float* __restrict__ ln3_b,
      const float* __restrict__ out_w, const float* __restrict__ out_b,
      float* __restrict__ tok_out, float* __restrict__ log_out, int L, int wt)
{
    __shared__ __align__(16) float xs[BB * HH / 2];   // 32KB staging
    __shared__ ull sbest[BB];
    int tid = threadIdx.x, lane = tid & 31, warp = tid >> 5;
    int bx = blockIdx.x, gw = bx * 8 + warp, gtid = bx * NT + tid;

    // launch-idempotent barrier init: read the quiescent generation
    unsigned gen;
    asm volatile("ld.relaxed.gpu.global.u32 %0, [%1];"
                 : "=r"(gen) : "l"(&g_flags[(bx & 31) * 64]));

    // ---- setup: PE table, argmax slots (both parities) ----
    for (int i = gtid; i < SMAX * DD; i += NB * NT) {
        int d = i & 511;
        double dv = exp((double)(d & ~1) * (-9.210340371976184 / 512.0));
        float arg = (float)(i >> 9) * (float)dv;
        g_pe[i] = (d & 1) ? cosf(arg) : sinf(arg);
    }
    if (gtid < 2 * 16 * BB) g_amax[gtid] = 0ull;
    gsync(gen, bx);

    // ---- cross-attn constant (Sk=1 => softmax==1) on blocks 0..15 ----
    if (bx < NLL * BB) {
        int l = bx >> 3, b = bx & 7;
        const float4* m4 = (const float4*)(memory + b * DD);
        for (int j = warp; j < DD; j += 8) {
            const float4* w4 = (const float4*)(ca_in_w + ((size_t)l * 3 * DD + 2 * DD + j) * DD);
            float acc = 0.f;
            #pragma unroll
            for (int k = 0; k < 4; k++) {
                float4 w = w4[lane + 32 * k], x = m4[lane + 32 * k];
                acc += w.x * x.x + w.y * x.y + w.z * x.z + w.w * x.w;
            }
            acc = wred(acc);
            if (lane == 0) xs[j] = acc + ca_in_b[l * 3 * DD + 2 * DD + j];
        }
        __syncthreads();
        for (int j = warp; j < DD; j += 8) {
            const float4* w4 = (const float4*)(ca_out_w + ((size_t)l * DD + j) * DD);
            const float4* v4 = (const float4*)xs;
            float acc = 0.f;
            #pragma unroll
            for (int k = 0; k < 4; k++) {
                float4 w = w4[lane + 32 * k], x = v4[lane + 32 * k];
                acc += w.x * x.x + w.y * x.y + w.z * x.z + w.w * x.w;
            }
            acc = wred(acc);
            if (lane == 0) g_cavec[(l * BB + b) * DD + j] = acc + ca_out_b[l * DD + j];
        }
    }
    gsync(gen, bx);

    for (int t = 0; t < L; t++) {
        int par = t & 1;
        for (int l = 0; l < NLL; l++) {
            // ---- QKV: 96 blocks, 768 warps x exactly 2 rows ----
            if (bx < 96) {
                int b = warp;
                float4 y[4];
                if (l == 0) {
                    int tok;
                    if (t == 0) {
                        tok = 1;
                    } else {
                        ull key = amax_slot_max(1 - par, b, lane);
                        tok = amax_tok(key);
                        if (bx == 0 && wt && lane == 0)
                            tok_out[b * L + (t - 1)] = (float)tok;
                    }
                    if (bx == 0 && tid < 16 * BB)
                        g_amax[par * 128 + tid] = 0ull;   // reset current-parity slots
                    const float4* e4 = (const float4*)(emb + (size_t)tok * DD);
                    const float4* p4 = (const float4*)(g_pe + t * DD);
                    #pragma unroll
                    for (int k = 0; k < 4; k++) {
                        float4 e = e4[lane + 32 * k], p = p4[lane + 32 * k];
                        y[k] = make_float4(e.x + p.x, e.y + p.y, e.z + p.z, e.w + p.w);
                    }
                } else {
                    #pragma unroll
                    for (int k = 0; k < 4; k++) {
                        float4 a = ((const float4*)(g_x2 + b * DD))[lane + 32 * k];
                        float4 c = ((const float4*)(g_f2 + b * DD))[lane + 32 * k];
                        y[k] = make_float4(a.x + c.x, a.y + c.y, a.z + c.z, a.w + c.w);
                    }
                    lnorm(y, ln3_g + (l - 1) * DD, ln3_b + (l - 1) * DD, lane);
                }
                #pragma unroll
                for (int k = 0; k < 4; k++) {
                    ((float4*)xs)[b * 128 + lane + 32 * k] = y[k];
                    if (bx == 0) ((float4*)g_x)[b * 128 + lane + 32 * k] = y[k];
                }
                __syncthreads();
                #pragma unroll
                for (int rr = 0; rr < 2; rr++) {
                    int j = gw + rr * 768;
                    float acc[8] = {0, 0, 0, 0, 0, 0, 0, 0};
                    dot8(sa_in_w + ((size_t)l * 3 * DD + j) * DD, xs, lane, acc);
                    float val = red8m(acc, lane);
                    if (lane < 8) {
                        val += sa_in_b[l * 3 * DD + j];
                        if (j < DD) g_q[lane * DD + j] = val;
                        else if (j < 2 * DD) {
                            int h = (j - DD) >> 6, d = (j - DD) & 63;
                            g_kc[(((l * BB + lane) * NHH + h) * SMAX + t) * HDD + d] = val;
                        } else {
                            int h = (j - 2 * DD) >> 6, d = (j - 2 * DD) & 63;
                            g_vc[(((l * BB + lane) * NHH + h) * SMAX + t) * HDD + d] = val;
                        }
                    }
                }
            }
            gsync(gen, bx);

            // ---- self-attn: 64 blocks, one (b,h) each; 8-warp PV split ----
            if (bx < 64) {
                int b = bx >> 3, h = bx & 7, n = t + 1;
                float* psh = xs;            // 64 probs (zero-padded)
                float* osh = xs + 64;       // 8 x 64 partial outputs
                const float* kb = g_kc + (size_t)(((l * BB + b) * NHH + h) * SMAX) * HDD;
                const float* vb = g_vc + (size_t)(((l * BB + b) * NHH + h) * SMAX) * HDD;
                if (warp == 0) {
                    const float4* q4 = (const float4*)(g_q + b * DD + h * HDD);
                    float s0 = -1e30f, s1 = -1e30f;
                    if (lane < n) {
                        const float4* k4 = (const float4*)(kb + (size_t)lane * HDD);
                        float a = 0.f;
                        #pragma unroll
                        for (int k = 0; k < 16; k++) {
                            float4 kk = k4[k], qq = q4[k];
                            a += kk.x * qq.x + kk.y * qq.y + kk.z * qq.z + kk.w * qq.w;
                        }
                        s0 = a * 0.125f;
                    }
                    if (lane + 32 < n) {
                        const float4* k4 = (const float4*)(kb + (size_t)(lane + 32) * HDD);
                        float a = 0.f;
                        #pragma unroll
                        for (int k = 0; k < 16; k++) {
                            float4 kk = k4[k], qq = q4[k];
                            a += kk.x * qq.x + kk.y * qq.y + kk.z * qq.z + kk.w * qq.w;
                        }
                        s1 = a * 0.125f;
                    }
                    float m = fmaxf(s0, s1);
                    #pragma unroll
                    for (int off = 16; off; off >>= 1)
                        m = fmaxf(m, __shfl_xor_sync(0xffffffffu, m, off));
                    float p0 = (lane < n) ? expf(s0 - m) : 0.f;
                    float p1 = (lane + 32 < n) ? expf(s1 - m) : 0.f;
                    float sum = wred(p0 + p1);
                    psh[lane] = p0;
                    psh[lane + 32] = p1;
                    if (lane == 0) xs[576] = sum;
                }
                __syncthreads();
                {   // all 8 warps: PV over j = warp + 8*i (probs zero beyond n)
                    float o0 = 0.f, o1 = 0.f;
                    #pragma unroll
                    for (int i = 0; i < 8; i++) {
                        int j = warp + i * 8;
                        float p = psh[j];
                        o0 += p * vb[(size_t)j * HDD + lane];
                        o1 += p * vb[(size_t)j * HDD + lane + 32];
                    }
                    osh[warp * 64 + lane] = o0;
                    osh[warp * 64 + lane + 32] = o1;
                }
                __syncthreads();
                if (warp == 0) {
                    float inv = 1.f / xs[576];
                    float a0 = 0.f, a1 = 0.f;
                    #pragma unroll
                    for (int w = 0; w < 8; w++) {
                        a0 += osh[w * 64 + lane];
                        a1 += osh[w * 64 + lane + 32];
                    }
                    g_att[b * DD + h * HDD + lane] = a0 * inv;
                    g_att[b * DD + h * HDD + lane + 32] = a1 * inv;
                }
            }
            gsync(gen, bx);

            // ---- attn out proj: 64 blocks, 512 warps x exactly 1 row ----
            if (bx < 64) {
                for (int i = tid; i < BB * DD / 4; i += NT)
                    ((float4*)xs)[i] = ((const float4*)g_att)[i];
                __syncthreads();
                int j = gw;
                float acc[8] = {0, 0, 0, 0, 0, 0, 0, 0};
                dot8(sa_out_w + ((size_t)l * DD + j) * DD, xs, lane, acc);
                float val = red8m(acc, lane);
                if (lane < 8) g_proj[lane * DD + j] = val + sa_out_b[l * DD + j];
            }
            gsync(gen, bx);

            // ---- LN1 -> +cavec -> LN2 -> FFN1: 128 blocks, 1024 warps x 2 rows ----
            {
                int b = warp;
                float4 y[4];
                #pragma unroll
                for (int k = 0; k < 4; k++) {
                    float4 a = ((const float4*)(g_x + b * DD))[lane + 32 * k];
                    float4 c = ((const float4*)(g_proj + b * DD))[lane + 32 * k];
                    y[k] = make_float4(a.x + c.x, a.y + c.y, a.z + c.z, a.w + c.w);
                }
                lnorm(y, ln1_g + l * DD, ln1_b + l * DD, lane);
                #pragma unroll
                for (int k = 0; k < 4; k++) {
                    float4 c = ((const float4*)(g_cavec + (l * BB + b) * DD))[lane + 32 * k];
                    y[k].x += c.x; y[k].y += c.y; y[k].z += c.z; y[k].w += c.w;
                }
                lnorm(y, ln2_g + l * DD, ln2_b + l * DD, lane);
                #pragma unroll
                for (int k = 0; k < 4; k++) {
                    ((float4*)xs)[b * 128 + lane + 32 * k] = y[k];
                    if (bx == 0) ((float4*)g_x2)[b * 128 + lane + 32 * k] = y[k];
                }
                __syncthreads();
                #pragma unroll
                for (int rr = 0; rr < 2; rr++) {
                    int j = gw + rr * 1024;
                    float acc[8] = {0, 0, 0, 0, 0, 0, 0, 0};
                    dot8(ff1_w + ((size_t)l * HH + j) * DD, xs, lane, acc);
                    float val = red8m(acc, lane);
                    if (lane < 8)
                        g_hbuf[lane * HH + j] = fmaxf(val + ff1_b[l * HH + j], 0.f);
                }
            }
            gsync(gen, bx);

            // ---- FFN2: 64 blocks, 512 warps x 1 row per half ----
            if (bx < 64) {
                #pragma unroll
                for (int half = 0; half < 2; half++) {
                    __syncthreads();
                    for (int i = tid; i < 4 * HH / 4; i += NT)
                        ((float4*)xs)[i] = ((const float4*)(g_hbuf + half * 4 * HH))[i];
                    __syncthreads();
                    int j = gw;
                    const float4* w4 = (const float4*)(ff2_w + ((size_t)l * DD + j) * HH);
                    const float4* x4 = (const float4*)xs;
                    float acc[4] = {0, 0, 0, 0};
                    #pragma unroll 4
                    for (int k = 0; k < 16; k++) {
                        float4 w = w4[lane + 32 * k];
                        #pragma unroll
                        for (int b = 0; b < 4; b++) {
                            float4 h = x4[b * 512 + lane + 32 * k];
                            acc[b] += w.x * h.x + w.y * h.y + w.z * h.z + w.w * h.w;
                        }
                    }
                    float val = red4m(acc, lane);
                    if (lane < 4)
                        g_f2[(half * 4 + lane) * DD + j] = val + ff2_b[l * DD + j];
                }
            }
            gsync(gen, bx);
        } // layers

        // ---- logits: 125 blocks, 1000 warps x exactly 8 groups of 4 rows ----
        if (bx < 125) {
            int b = warp;
            float4 y[4];
            #pragma unroll
            for (int k = 0; k < 4; k++) {
                float4 a = ((const float4*)(g_x2 + b * DD))[lane + 32 * k];
                float4 c = ((const float4*)(g_f2 + b * DD))[lane + 32 * k];
                y[k] = make_float4(a.x + c.x, a.y + c.y, a.z + c.z, a.w + c.w);
            }
            lnorm(y, ln3_g + (NLL - 1) * DD, ln3_b + (NLL - 1) * DD, lane);
            #pragma unroll
            for (int k = 0; k < 4; k++)
                ((float4*)xs)[b * 128 + lane + 32 * k] = y[k];
            if (tid < BB) sbest[tid] = 0ull;
            __syncthreads();

            const ulonglong2* hsu = (const ulonglong2*)xs;
            int myb = lane & 7, myr = lane >> 3;
            ull bestk = 0ull;
            #pragma unroll 1
            for (int g = 0; g < 8; g++) {
                int v0 = (gw * 8 + g) * 4;
                const ulonglong2* wu = (const ulonglong2*)(out_w + (size_t)v0 * DD);
                ull acc[4][8];
                #pragma unroll
                for (int r = 0; r < 4; r++)
                    #pragma unroll
                    for (int bb = 0; bb < 8; bb++) acc[r][bb] = 0ull;
                #pragma unroll
                for (int k = 0; k < 4; k++) {
                    ulonglong2 h[8];
                    #pragma unroll
                    for (int bb = 0; bb < 8; bb++) h[bb] = hsu[bb * 128 + lane + 32 * k];
                    #pragma unroll
                    for (int r = 0; r < 4; r++) {
                        ulonglong2 w = wu[r * 128 + lane + 32 * k];
                        #pragma unroll
                        for (int bb = 0; bb < 8; bb++) {
                            acc[r][bb] = ffma2(w.x, h[bb].x, acc[r][bb]);
                            acc[r][bb] = ffma2(w.y, h[bb].y, acc[r][bb]);
                        }
                    }
                }
                float a[32];
                #pragma unroll
                for (int r = 0; r < 4; r++)
                    #pragma unroll
                    for (int bb = 0; bb < 8; bb++) a[r * 8 + bb] = f2sum(acc[r][bb]);
                #pragma unroll
                for (int s = 0; s < 5; s++) {
                    int off = 1 << s, n = 32 >> (s + 1);
                    #pragma unroll
                    for (int i = 0; i < n; i++) {
                        float x = (lane & off) ? a[2 * i] : a[2 * i + 1];
                        float rc = __shfl_xor_sync(0xffffffffu, x, off);
                        a[i] = ((lane & off) ? a[2 * i + 1] : a[2 * i]) + rc;
                    }
                }
                int v = v0 + myr;
                float val = a[0] + out_b[v];
                log_out[((size_t)myb * L + t) * VV + v] = val;
                unsigned u = __float_as_uint(val);
                u = (u & 0x80000000u) ? ~u : (u | 0x80000000u);
                ull key = ((ull)u << 32) | (unsigned)(0xFFFFFFFFu - (unsigned)v);
                if (key > bestk) bestk = key;
            }
            ull o = __shfl_xor_sync(0xffffffffu, bestk, 8);  if (o > bestk) bestk = o;
            o     = __shfl_xor_sync(0xffffffffu, bestk, 16); if (o > bestk) bestk = o;
            if (myr == 0) atomicMax(&sbest[myb], bestk);
            __syncthreads();
            // shadow-slot atomics: contention 125 -> ~8 per address
            if (tid < BB)
                atomicMax(&g_amax[par * 128 + (bx & 15) * 8 + tid], sbest[tid]);
        }
        gsync(gen, bx);   // doubles as next step's pre-QKV barrier
    } // t

    // final token (decided by step L-1's logits)
    if (bx == 0 && warp < BB && wt) {
        ull key = amax_slot_max((L - 1) & 1, warp, lane);
        if (lane == 0) tok_out[warp * L + (L - 1)] = (float)amax_tok(key);
    }
}

extern "C" void kernel_launch(void* const* d_in, const int* in_sizes, int n_in,
                              void* d_out, int out_size) {
    (void)in_sizes; (void)n_in;
    int L, wt;
    if (out_size % (BB * (VV + 1)) == 0) { L = out_size / (BB * (VV + 1)); wt = 1; }
    else if (out_size % (BB * VV) == 0)  { L = out_size / (BB * VV);       wt = 0; }
    else                                 { L = 48;                         wt = 1; }
    if (L > SMAX - 1) L = SMAX - 1;
    if (L <= 0) return;

    float* out_f = (float*)d_out;
    float* tok_out = out_f;
    float* log_out = wt ? (out_f + (size_t)BB * L) : out_f;

    kmain<<<NB, NT>>>(
        (const float*)d_in[0],  (const float*)d_in[1],  (const float*)d_in[2],
        (const float*)d_in[3],  (const float*)d_in[4],  (const float*)d_in[5],
        (const float*)d_in[6],  (const float*)d_in[7],  (const float*)d_in[8],
        (const float*)d_in[9],  (const float*)d_in[10], (const float*)d_in[11],
        (const float*)d_in[12], (const float*)d_in[13], (const float*)d_in[14],
        (const float*)d_in[15], (const float*)d_in[16], (const float*)d_in[17],
        (const float*)d_in[18], (const float*)d_in[19], (const float*)d_in[20],
        (const float*)d_in[21], tok_out, log_out, L, wt);
}

// round 15
// speedup vs baseline: 3.1769x; 1.0443x over previous
#include <cuda_runtime.h>
#include <math.h>

#define BB 8
#define DD 512
#define NHH 8
#define HDD 64
#define HH 2048
#define NLL 2
#define VV 32000
#define SMAX 64
#define EPSL 1e-5f
#define NB 128
#define NT 256

typedef unsigned long long ull;

__device__ float g_pe[SMAX*DD];
__device__ float g_x[BB*DD];
__device__ float g_x2[BB*DD];
__device__ float g_q[BB*DD];
__device__ float g_pp[BB*NHH*DD];       // per-head projection partials
__device__ float g_hbuf[BB*HH];
__device__ float g_f2[BB*DD];
__device__ float g_kc[NLL*BB*NHH*SMAX*HDD];
__device__ float g_vc[NLL*BB*NHH*SMAX*HDD];
__device__ float g_cavec[NLL*BB*DD];
__device__ ull   g_amax[2*16*BB];       // parity x 16 shadow slots x batch
__device__ unsigned g_cnt;              // monotonic arrival counter (never reset)
__device__ unsigned g_flags[32*64];     // release flags, 256B apart (monotonic)

__device__ __forceinline__ float wred(float v) {
    v += __shfl_xor_sync(0xffffffffu, v, 16);
    v += __shfl_xor_sync(0xffffffffu, v, 8);
    v += __shfl_xor_sync(0xffffffffu, v, 4);
    v += __shfl_xor_sync(0xffffffffu, v, 2);
    v += __shfl_xor_sync(0xffffffffu, v, 1);
    return v;
}

// Grid barrier (R11/R14-proven, unchanged).
__device__ __forceinline__ void gsync(unsigned &gen, int bx) {
    __syncthreads();
    if (threadIdx.x == 0) {
        unsigned target = gen + 1;
        asm volatile("fence.acq_rel.gpu;" ::: "memory");          // release
        if (atomicAdd(&g_cnt, 1u) == NB * target - 1u) {
            asm volatile("fence.acq_rel.gpu;" ::: "memory");
            #pragma unroll
            for (int i = 0; i < 32; i++)
                asm volatile("st.relaxed.gpu.global.u32 [%0], %1;"
                             :: "l"(&g_flags[i * 64]), "r"(target) : "memory");
        } else {
            unsigned cur;
            unsigned* fl = &g_flags[(bx & 31) * 64];
            do {
                asm volatile("ld.relaxed.gpu.global.u32 %0, [%1];"
                             : "=r"(cur) : "l"(fl));
            } while ((int)(cur - target) < 0);                    // wrap-safe
        }
        asm volatile("fence.acq_rel.gpu;" ::: "memory");          // acquire
    }
    gen = gen + 1;
    __syncthreads();
}

__device__ __forceinline__ ull ffma2(ull a, ull b, ull c) {
    ull d;
    asm("fma.rn.f32x2 %0, %1, %2, %3;" : "=l"(d) : "l"(a), "l"(b), "l"(c));
    return d;
}
__device__ __forceinline__ float f2sum(ull a) {
    return __uint_as_float((unsigned)a) + __uint_as_float((unsigned)(a >> 32));
}

__device__ __forceinline__ void lnorm(float4* y, const float* gam, const float* bet, int lane) {
    float s = 0.f;
    #pragma unroll
    for (int k = 0; k < 4; k++) s += y[k].x + y[k].y + y[k].z + y[k].w;
    float m = wred(s) * (1.f / DD);
    float v = 0.f;
    #pragma unroll
    for (int k = 0; k < 4; k++) {
        float a = y[k].x - m, b = y[k].y - m, c = y[k].z - m, d = y[k].w - m;
        v += a * a + b * b + c * c + d * d;
    }
    v = wred(v) * (1.f / DD);
    float r = 1.f / sqrtf(v + EPSL);
    #pragma unroll
    for (int k = 0; k < 4; k++) {
        float4 g = ((const float4*)gam)[lane + 32 * k];
        float4 b4 = ((const float4*)bet)[lane + 32 * k];
        y[k].x = (y[k].x - m) * r * g.x + b4.x;
        y[k].y = (y[k].y - m) * r * g.y + b4.y;
        y[k].z = (y[k].z - m) * r * g.z + b4.z;
        y[k].w = (y[k].w - m) * r * g.w + b4.w;
    }
}

__device__ __forceinline__ void dot8(const float* __restrict__ w, const float* xs,
                                     int lane, float* acc) {
    const float4* w4 = (const float4*)w;
    const float4* x4 = (const float4*)xs;
    #pragma unroll
    for (int k = 0; k < 4; k++) {
        float4 ww = w4[lane + 32 * k];
        #pragma unroll
        for (int b = 0; b < 8; b++) {
            float4 h = x4[b * 128 + lane + 32 * k];
            acc[b] += ww.x * h.x + ww.y * h.y + ww.z * h.z + ww.w * h.w;
        }
    }
}

// butterfly-merge: lane L ends with the full sum of a[L&7]
__device__ __forceinline__ float red8m(float* a, int lane) {
    #pragma unroll
    for (int s = 0; s < 3; s++) {
        int off = 1 << s, n = 8 >> (s + 1);
        #pragma unroll
        for (int i = 0; i < n; i++) {
            float x = (lane & off) ? a[2 * i] : a[2 * i + 1];
            float rc = __shfl_xor_sync(0xffffffffu, x, off);
            a[i] = ((lane & off) ? a[2 * i + 1] : a[2 * i]) + rc;
        }
    }
    float v = a[0];
    v += __shfl_xor_sync(0xffffffffu, v, 8);
    v += __shfl_xor_sync(0xffffffffu, v, 16);
    return v;
}
__device__ __forceinline__ float red4m(float* a, int lane) {
    #pragma unroll
    for (int s = 0; s < 2; s++) {
        int off = 1 << s, n = 4 >> (s + 1);
        #pragma unroll
        for (int i = 0; i < n; i++) {
            float x = (lane & off) ? a[2 * i] : a[2 * i + 1];
            float rc = __shfl_xor_sync(0xffffffffu, x, off);
            a[i] = ((lane & off) ? a[2 * i + 1] : a[2 * i]) + rc;
        }
    }
    float v = a[0];
    v += __shfl_xor_sync(0xffffffffu, v, 4);
    v += __shfl_xor_sync(0xffffffffu, v, 8);
    v += __shfl_xor_sync(0xffffffffu, v, 16);
    return v;
}

__device__ __forceinline__ int amax_tok(ull key) {
    return (int)(0xFFFFFFFFu - (unsigned)(key & 0xFFFFFFFFull));
}

// max over 16 shadow slots for (parity parX, batch b); result on ALL lanes
__device__ __forceinline__ ull amax_slot_max(int parX, int b, int lane) {
    ull k = (lane < 16) ? g_amax[parX * 128 + lane * 8 + b] : 0ull;
    #pragma unroll
    for (int off = 1; off <= 8; off <<= 1) {
        ull o = __shfl_xor_sync(0xffffffffu, k, off);
        if (o > k) k = o;
    }
    ull o = __shfl_xor_sync(0xffffffffu, k, 16);
    if (o > k) k = o;
    return k;
}

__global__ void __launch_bounds__(NT)
kmain(const float* __restrict__ memory, const float* __restrict__ emb,
      const float* __restrict__ sa_in_w, const float* __restrict__ sa_in_b,
      const float* __restrict__ sa_out_w, const float* __restrict__ sa_out_b,
      const float* __restrict__ ca_in_w, const float* __restrict__ ca_in_b,
      const float* __restrict__ ca_out_w, const float* __restrict__ ca_out_b,
      const float* __restrict__ ff1_w, const float* __restrict__ ff1_b,
      const float* __restrict__ ff2_w, const float* __restrict__ ff2_b,
      const float* __restrict__ ln1_g, const float* __restrict__ ln1_b,
      const float* __restrict__ ln2_g, const float* __restrict__ ln2_b,
      const float* __restrict__ ln3_g, const float* __restrict__ ln3_b,
      const float* __restrict__ out_w, const float* __restrict__ out_b,
      float* __restrict__ tok_out, float* __restrict__ log_out, int L, int wt)
{
    __shared__ __align__(16) float xs[BB * HH / 2];   // 32KB staging
    __shared__ ull sbest[BB];
    int tid = threadIdx.x, lane = tid & 31, warp = tid >> 5;
    int bx = blockIdx.x, gw = bx * 8 + warp, gtid = bx * NT + tid;

    // launch-idempotent barrier init: read the quiescent generation
    unsigned gen;
    asm volatile("ld.relaxed.gpu.global.u32 %0, [%1];"
                 : "=r"(gen) : "l"(&g_flags[(bx & 31) * 64]));

    // ---- setup: PE table, argmax slots (both parities) ----
    for (int i = gtid; i < SMAX * DD; i += NB * NT) {
        int d = i & 511;
        double dv = exp((double)(d & ~1) * (-9.210340371976184 / 512.0));
        float arg = (float)(i >> 9) * (float)dv;
        g_pe[i] = (d & 1) ? cosf(arg) : sinf(arg);
    }
    if (gtid < 2 * 16 * BB) g_amax[gtid] = 0ull;
    gsync(gen, bx);

    // ---- cross-attn constant (Sk=1 => softmax==1) on blocks 0..15 ----
    if (bx < NLL * BB) {
        int l = bx >> 3, b = bx & 7;
        const float4* m4 = (const float4*)(memory + b * DD);
        for (int j = warp; j < DD; j += 8) {
            const float4* w4 = (const float4*)(ca_in_w + ((size_t)l * 3 * DD + 2 * DD + j) * DD);
            float acc = 0.f;
            #pragma unroll
            for (int k = 0; k < 4; k++) {
                float4 w = w4[lane + 32 * k], x = m4[lane + 32 * k];
                acc += w.x * x.x + w.y * x.y + w.z * x.z + w.w * x.w;
            }
            acc = wred(acc);
            if (lane == 0) xs[j] = acc + ca_in_b[l * 3 * DD + 2 * DD + j];
        }
        __syncthreads();
        for (int j = warp; j < DD; j += 8) {
            const float4* w4 = (const float4*)(ca_out_w + ((size_t)l * DD + j) * DD);
            const float4* v4 = (const float4*)xs;
            float acc = 0.f;
            #pragma unroll
            for (int k = 0; k < 4; k++) {
                float4 w = w4[lane + 32 * k], x = v4[lane + 32 * k];
                acc += w.x * x.x + w.y * x.y + w.z * x.z + w.w * x.w;
            }
            acc = wred(acc);
            if (lane == 0) g_cavec[(l * BB + b) * DD + j] = acc + ca_out_b[l * DD + j];
        }
    }
    gsync(gen, bx);

    for (int t = 0; t < L; t++) {
        int par = t & 1;
        for (int l = 0; l < NLL; l++) {
            // ---- QKV: 96 blocks, 768 warps x exactly 2 rows ----
            if (bx < 96) {
                int b = warp;
                float4 y[4];
                if (l == 0) {
                    int tok;
                    if (t == 0) {
                        tok = 1;
                    } else {
                        ull key = amax_slot_max(1 - par, b, lane);
                        tok = amax_tok(key);
                        if (bx == 0 && wt && lane == 0)
                            tok_out[b * L + (t - 1)] = (float)tok;
                    }
                    if (bx == 0 && tid < 16 * BB)
                        g_amax[par * 128 + tid] = 0ull;
                    const float4* e4 = (const float4*)(emb + (size_t)tok * DD);
                    const float4* p4 = (const float4*)(g_pe + t * DD);
                    #pragma unroll
                    for (int k = 0; k < 4; k++) {
                        float4 e = e4[lane + 32 * k], p = p4[lane + 32 * k];
                        y[k] = make_float4(e.x + p.x, e.y + p.y, e.z + p.z, e.w + p.w);
                    }
                } else {
                    #pragma unroll
                    for (int k = 0; k < 4; k++) {
                        float4 a = ((const float4*)(g_x2 + b * DD))[lane + 32 * k];
                        float4 c = ((const float4*)(g_f2 + b * DD))[lane + 32 * k];
                        y[k] = make_float4(a.x + c.x, a.y + c.y, a.z + c.z, a.w + c.w);
                    }
                    lnorm(y, ln3_g + (l - 1) * DD, ln3_b + (l - 1) * DD, lane);
                }
                #pragma unroll
                for (int k = 0; k < 4; k++) {
                    ((float4*)xs)[b * 128 + lane + 32 * k] = y[k];
                    if (bx == 0) ((float4*)g_x)[b * 128 + lane + 32 * k] = y[k];
                }
                __syncthreads();
                #pragma unroll
                for (int rr = 0; rr < 2; rr++) {
                    int j = gw + rr * 768;
                    float acc[8] = {0, 0, 0, 0, 0, 0, 0, 0};
                    dot8(sa_in_w + ((size_t)l * 3 * DD + j) * DD, xs, lane, acc);
                    float val = red8m(acc, lane);
                    if (lane < 8) {
                        val += sa_in_b[l * 3 * DD + j];
                        if (j < DD) g_q[lane * DD + j] = val;
                        else if (j < 2 * DD) {
                            int h = (j - DD) >> 6, d = (j - DD) & 63;
                            g_kc[(((l * BB + lane) * NHH + h) * SMAX + t) * HDD + d] = val;
                        } else {
                            int h = (j - 2 * DD) >> 6, d = (j - 2 * DD) & 63;
                            g_vc[(((l * BB + lane) * NHH + h) * SMAX + t) * HDD + d] = val;
                        }
                    }
                }
            }
            gsync(gen, bx);

            // ---- self-attn + proj partial: 128 blocks, 2 per (b,h) ----
            {
                int pr = bx & 1;            // which 256-dim half of proj this block does
                int bh = bx >> 1;
                int b = bh >> 3, h = bh & 7, n = t + 1;
                float* psh = xs;            // 64 probs (zero-padded)
                float* osh = xs + 64;       // 8 x 64 partial PV outputs
                float* ohd = xs + 640;      // 64 final head output
                const float* kb = g_kc + (size_t)(((l * BB + b) * NHH + h) * SMAX) * HDD;
                const float* vb = g_vc + (size_t)(((l * BB + b) * NHH + h) * SMAX) * HDD;
                if (warp == 0) {
                    const float4* q4 = (const float4*)(g_q + b * DD + h * HDD);
                    float s0 = -1e30f, s1 = -1e30f;
                    if (lane < n) {
                        const float4* k4 = (const float4*)(kb + (size_t)lane * HDD);
                        float a = 0.f;
                        #pragma unroll
                        for (int k = 0; k < 16; k++) {
                            float4 kk = k4[k], qq = q4[k];
                            a += kk.x * qq.x + kk.y * qq.y + kk.z * qq.z + kk.w * qq.w;
                        }
                        s0 = a * 0.125f;
                    }
                    if (lane + 32 < n) {
                        const float4* k4 = (const float4*)(kb + (size_t)(lane + 32) * HDD);
                        float a = 0.f;
                        #pragma unroll
                        for (int k = 0; k < 16; k++) {
                            float4 kk = k4[k], qq = q4[k];
                            a += kk.x * qq.x + kk.y * qq.y + kk.z * qq.z + kk.w * qq.w;
                        }
                        s1 = a * 0.125f;
                    }
                    float m = fmaxf(s0, s1);
                    #pragma unroll
                    for (int off = 16; off; off >>= 1)
                        m = fmaxf(m, __shfl_xor_sync(0xffffffffu, m, off));
                    float p0 = (lane < n) ? expf(s0 - m) : 0.f;
                    float p1 = (lane + 32 < n) ? expf(s1 - m) : 0.f;
                    float sum = wred(p0 + p1);
                    psh[lane] = p0;
                    psh[lane + 32] = p1;
                    if (lane == 0) xs[704] = sum;
                }
                __syncthreads();
                {   // 8 warps split PV (probs zero beyond n)
                    float o0 = 0.f, o1 = 0.f;
                    #pragma unroll
                    for (int i = 0; i < 8; i++) {
                        int j = warp + i * 8;
                        float p = psh[j];
                        o0 += p * vb[(size_t)j * HDD + lane];
                        o1 += p * vb[(size_t)j * HDD + lane + 32];
                    }
                    osh[warp * 64 + lane] = o0;
                    osh[warp * 64 + lane + 32] = o1;
                }
                __syncthreads();
                if (warp == 0) {
                    float inv = 1.f / xs[704];
                    float a0 = 0.f, a1 = 0.f;
                    #pragma unroll
                    for (int w = 0; w < 8; w++) {
                        a0 += osh[w * 64 + lane];
                        a1 += osh[w * 64 + lane + 32];
                    }
                    ohd[lane] = a0 * inv;
                    ohd[lane + 32] = a1 * inv;
                }
                __syncthreads();
                // rank-64 projection partial: this block's 256-dim half
                {
                    int dd = pr * 256 + warp * 32 + lane;   // 1 dim per thread
                    const float4* w4 = (const float4*)(sa_out_w
                        + ((size_t)l * DD + dd) * DD + h * HDD);
                    const float4* o4 = (const float4*)ohd;  // broadcast
                    float acc = 0.f;
                    #pragma unroll
                    for (int k = 0; k < 16; k++) {
                        float4 w = w4[k], o = o4[k];
                        acc += w.x * o.x + w.y * o.y + w.z * o.z + w.w * o.w;
                    }
                    g_pp[((size_t)b * NHH + h) * DD + dd] = acc;
                }
            }
            gsync(gen, bx);

            // ---- LN1(x + Σ_h pp + out_b) -> +cavec -> LN2 -> FFN1 ----
            {
                int b = warp;
                float4 y[4];
                #pragma unroll
                for (int k = 0; k < 4; k++) {
                    float4 a = ((const float4*)(g_x + b * DD))[lane + 32 * k];
                    float4 s = ((const float4*)(sa_out_b + l * DD))[lane + 32 * k];
                    y[k] = make_float4(a.x + s.x, a.y + s.y, a.z + s.z, a.w + s.w);
                    #pragma unroll
                    for (int h = 0; h < NHH; h++) {
                        float4 p = ((const float4*)(g_pp + ((size_t)b * NHH + h) * DD))[lane + 32 * k];
                        y[k].x += p.x; y[k].y += p.y; y[k].z += p.z; y[k].w += p.w;
                    }
                }
                lnorm(y, ln1_g + l * DD, ln1_b + l * DD, lane);
                #pragma unroll
                for (int k = 0; k < 4; k++) {
                    float4 c = ((const float4*)(g_cavec + (l * BB + b) * DD))[lane + 32 * k];
                    y[k].x += c.x; y[k].y += c.y; y[k].z += c.z; y[k].w += c.w;
                }
                lnorm(y, ln2_g + l * DD, ln2_b + l * DD, lane);
                #pragma unroll
                for (int k = 0; k < 4; k++) {
                    ((float4*)xs)[b * 128 + lane + 32 * k] = y[k];
                    if (bx == 0) ((float4*)g_x2)[b * 128 + lane + 32 * k] = y[k];
                }
                __syncthreads();
                #pragma unroll
                for (int rr = 0; rr < 2; rr++) {
                    int j = gw + rr * 1024;
                    float acc[8] = {0, 0, 0, 0, 0, 0, 0, 0};
                    dot8(ff1_w + ((size_t)l * HH + j) * DD, xs, lane, acc);
                    float val = red8m(acc, lane);
                    if (lane < 8)
                        g_hbuf[lane * HH + j] = fmaxf(val + ff1_b[l * HH + j], 0.f);
                }
            }
            gsync(gen, bx);

            // ---- FFN2: 128 blocks, each one half, 1024 warps x exactly 1 row ----
            {
                int half = bx >> 6;                    // 0..1 (batches half*4..half*4+3)
                for (int i = tid; i < 4 * HH / 4; i += NT)
                    ((float4*)xs)[i] = ((const float4*)(g_hbuf + half * 4 * HH))[i];
                __syncthreads();
                int j = (bx & 63) * 8 + warp;          // 0..511
                const float4* w4 = (const float4*)(ff2_w + ((size_t)l * DD + j) * HH);
                const float4* x4 = (const float4*)xs;
                float acc[4] = {0, 0, 0, 0};
                #pragma unroll 4
                for (int k = 0; k < 16; k++) {
                    float4 w = w4[lane + 32 * k];
                    #pragma unroll
                    for (int b = 0; b < 4; b++) {
                        float4 h = x4[b * 512 + lane + 32 * k];
                        acc[b] += w.x * h.x + w.y * h.y + w.z * h.z + w.w * h.w;
                    }
                }
                float val = red4m(acc, lane);
                if (lane < 4)
                    g_f2[(half * 4 + lane) * DD + j] = val + ff2_b[l * DD + j];
            }
            gsync(gen, bx);
        } // layers

        // ---- logits: 125 blocks, 1000 warps x exactly 8 groups of 4 rows ----
        if (bx < 125) {
            int b = warp;
            float4 y[4];
            #pragma unroll
            for (int k = 0; k < 4; k++) {
                float4 a = ((const float4*)(g_x2 + b * DD))[lane + 32 * k];
                float4 c = ((const float4*)(g_f2 + b * DD))[lane + 32 * k];
                y[k] = make_float4(a.x + c.x, a.y + c.y, a.z + c.z, a.w + c.w);
            }
            lnorm(y, ln3_g + (NLL - 1) * DD, ln3_b + (NLL - 1) * DD, lane);
            #pragma unroll
            for (int k = 0; k < 4; k++)
                ((float4*)xs)[b * 128 + lane + 32 * k] = y[k];
            if (tid < BB) sbest[tid] = 0ull;
            __syncthreads();

            const ulonglong2* hsu = (const ulonglong2*)xs;
            int myb = lane & 7, myr = lane >> 3;
            ull bestk = 0ull;
            #pragma unroll 1
            for (int g = 0; g < 8; g++) {
                int v0 = (gw * 8 + g) * 4;
                const ulonglong2* wu = (const ulonglong2*)(out_w + (size_t)v0 * DD);
                ull acc[4][8];
                #pragma unroll
                for (int r = 0; r < 4; r++)
                    #pragma unroll
                    for (int bb = 0; bb < 8; bb++) acc[r][bb] = 0ull;
                #pragma unroll
                for (int k = 0; k < 4; k++) {
                    ulonglong2 h[8];
                    #pragma unroll
                    for (int bb = 0; bb < 8; bb++) h[bb] = hsu[bb * 128 + lane + 32 * k];
                    #pragma unroll
                    for (int r = 0; r < 4; r++) {
                        ulonglong2 w = wu[r * 128 + lane + 32 * k];
                        #pragma unroll
                        for (int bb = 0; bb < 8; bb++) {
                            acc[r][bb] = ffma2(w.x, h[bb].x, acc[r][bb]);
                            acc[r][bb] = ffma2(w.y, h[bb].y, acc[r][bb]);
                        }
                    }
                }
                float a[32];
                #pragma unroll
                for (int r = 0; r < 4; r++)
                    #pragma unroll
                    for (int bb = 0; bb < 8; bb++) a[r * 8 + bb] = f2sum(acc[r][bb]);
                #pragma unroll
                for (int s = 0; s < 5; s++) {
                    int off = 1 << s, n = 32 >> (s + 1);
                    #pragma unroll
                    for (int i = 0; i < n; i++) {
                        float x = (lane & off) ? a[2 * i] : a[2 * i + 1];
                        float rc = __shfl_xor_sync(0xffffffffu, x, off);
                        a[i] = ((lane & off) ? a[2 * i + 1] : a[2 * i]) + rc;
                    }
                }
                int v = v0 + myr;
                float val = a[0] + out_b[v];
                log_out[((size_t)myb * L + t) * VV + v] = val;
                unsigned u = __float_as_uint(val);
                u = (u & 0x80000000u) ? ~u : (u | 0x80000000u);
                ull key = ((ull)u << 32) | (unsigned)(0xFFFFFFFFu - (unsigned)v);
                if (key > bestk) bestk = key;
            }
            ull o = __shfl_xor_sync(0xffffffffu, bestk, 8);  if (o > bestk) bestk = o;
            o     = __shfl_xor_sync(0xffffffffu, bestk, 16); if (o > bestk) bestk = o;
            if (myr == 0) atomicMax(&sbest[myb], bestk);
            __syncthreads();
            if (tid < BB)
                atomicMax(&g_amax[par * 128 + (bx & 15) * 8 + tid], sbest[tid]);
        }
        gsync(gen, bx);   // doubles as next step's pre-QKV barrier
    } // t

    // final token (decided by step L-1's logits)
    if (bx == 0 && warp < BB && wt) {
        ull key = amax_slot_max((L - 1) & 1, warp, lane);
        if (lane == 0) tok_out[warp * L + (L - 1)] = (float)amax_tok(key);
    }
}

extern "C" void kernel_launch(void* const* d_in, const int* in_sizes, int n_in,
                              void* d_out, int out_size) {
    (void)in_sizes; (void)n_in;
    int L, wt;
    if (out_size % (BB * (VV + 1)) == 0) { L = out_size / (BB * (VV + 1)); wt = 1; }
    else if (out_size % (BB * VV) == 0)  { L = out_size / (BB * VV);       wt = 0; }
    else                                 { L = 48;                         wt = 1; }
    if (L > SMAX - 1) L = SMAX - 1;
    if (L <= 0) return;

    float* out_f = (float*)d_out;
    float* tok_out = out_f;
    float* log_out = wt ? (out_f + (size_t)BB * L) : out_f;

    kmain<<<NB, NT>>>(
        (const float*)d_in[0],  (const float*)d_in[1],  (const float*)d_in[2],
        (const float*)d_in[3],  (const float*)d_in[4],  (const float*)d_in[5],
        (const float*)d_in[6],  (const float*)d_in[7],  (const float*)d_in[8],
        (const float*)d_in[9],  (const float*)d_in[10], (const float*)d_in[11],
        (const float*)d_in[12], (const float*)d_in[13], (const float*)d_in[14],
        (const float*)d_in[15], (const float*)d_in[16], (const float*)d_in[17],
        (const float*)d_in[18], (const float*)d_in[19], (const float*)d_in[20],
        (const float*)d_in[21], tok_out, log_out, L, wt);
}